// round 3
// baseline (speedup 1.0000x reference)
#include <cuda_runtime.h>

typedef unsigned long long u64;

#define D       32
#define KNN     4
#define SPB     16        // samples per block
#define PIECES  8         // center shards per block (2 per warp: lane-half h)
#define TILE    32        // centers staged per piece per step

// ---------------- packed f32x2 helpers (sm_103a FFMA2 path) ----------------
__device__ __forceinline__ u64 fma2(u64 a, u64 b, u64 c) {
    u64 r;
    asm("fma.rn.f32x2 %0, %1, %2, %3;" : "=l"(r) : "l"(a), "l"(b), "l"(c));
    return r;
}
__device__ __forceinline__ u64 add2(u64 a, u64 b) {
    u64 r;
    asm("add.rn.f32x2 %0, %1, %2;" : "=l"(r) : "l"(a), "l"(b));
    return r;
}
__device__ __forceinline__ void unpack2(u64 a, float& lo, float& hi) {
    asm("mov.b64 {%0, %1}, %2;" : "=f"(lo), "=f"(hi) : "l"(a));
}

// ---------------- scratch: per-center squared norms ----------------
__device__ float g_cnorm[4096];

__global__ void cnorm_kernel(const float* __restrict__ ctrs, int n_fcns) {
    int f = blockIdx.x * blockDim.x + threadIdx.x;
    if (f < n_fcns) {
        const float4* c4 = (const float4*)(ctrs + (size_t)f * D);
        float s = 0.0f;
#pragma unroll
        for (int j = 0; j < D / 4; j++) {
            float4 q = __ldg(c4 + j);
            s += q.x * q.x + q.y * q.y + q.z * q.z + q.w * q.w;
        }
        g_cnorm[f] = s;
    }
}

// ---------------- main fused kernel ----------------
// Block = 128 threads = 4 warps, 16 samples. Lane = (s = lane&15, h = lane>>4).
// Phase A: lane scans piece (2*w + h): centers [piece*PIECE_SZ, +PIECE_SZ),
//          keeping a private top-4 for sample s. 8 pieces x 4 = 32 candidates
//          per sample, merged lexicographically (dist, idx).
// Phase B: warp w applies models for samples [4w, 4w+4) warp-cooperatively.
__global__ __launch_bounds__(128) void pwl_kernel(
    const float* __restrict__ x,
    const float* __restrict__ ctrs,
    const float* __restrict__ wts,
    const float* __restrict__ offs,
    float* __restrict__ y,
    int n_fcns)
{
    __shared__ __align__(16) float s_ctr[PIECES][TILE * D];  // 32 KB
    __shared__ float s_cn[PIECES][TILE];
    __shared__ float s_x[SPB][D + 1];
    __shared__ float s_cd[SPB][PIECES * KNN];
    __shared__ int   s_ci[SPB][PIECES * KNN];
    __shared__ int   s_idx[SPB][KNN];

    const int lane = threadIdx.x & 31;
    const int w    = threadIdx.x >> 5;
    const int s    = lane & 15;
    const int h    = lane >> 4;
    const int piece = 2 * w + h;
    const int srow = blockIdx.x * SPB + s;

    // ---- load this lane's x row into registers (packed pairs); h==0 -> smem ----
    u64 xp[16];
    {
        const ulonglong2* xg = (const ulonglong2*)(x + (size_t)srow * D);
#pragma unroll
        for (int j = 0; j < 8; j++) {
            ulonglong2 q = __ldg(xg + j);
            xp[2 * j]     = q.x;
            xp[2 * j + 1] = q.y;
            if (h == 0) {
                float a, b;
                unpack2(q.x, a, b);
                s_x[s][4 * j + 0] = a;
                s_x[s][4 * j + 1] = b;
                unpack2(q.y, a, b);
                s_x[s][4 * j + 2] = a;
                s_x[s][4 * j + 3] = b;
            }
        }
    }

    // ---- phase A: scan this lane's piece, keep stable top-4 ----
    const int piece_sz = n_fcns / PIECES;        // 256 for n_fcns=2048
    const int fstart   = piece * piece_sz;

    float bd0 = 3.4e38f, bd1 = 3.4e38f, bd2 = 3.4e38f, bd3 = 3.4e38f;
    int   bi0 = 0, bi1 = 0, bi2 = 0, bi3 = 0;

    for (int t = 0; t < piece_sz; t += TILE) {
        __syncwarp();
        // warp w stages tiles for its two pieces (2w, 2w+1); private to warp.
#pragma unroll
        for (int pp = 0; pp < 2; pp++) {
            const int p     = 2 * w + pp;
            const int gbase = p * piece_sz + t;
            const float4* g4  = (const float4*)(ctrs + (size_t)gbase * D);
            float4*       sc4 = (float4*)s_ctr[p];
#pragma unroll
            for (int i = 0; i < TILE * D / 4 / 32; i++)          // 8 iters
                sc4[i * 32 + lane] = __ldg(g4 + i * 32 + lane);
            s_cn[p][lane] = g_cnorm[gbase + lane];               // TILE==32
        }
        __syncwarp();

#pragma unroll 2
        for (int ff = 0; ff < TILE; ff++) {
            const ulonglong2* c2 = (const ulonglong2*)(s_ctr[piece] + ff * D);
            u64 a0 = 0ull, a1 = 0ull, a2 = 0ull, a3 = 0ull;
#pragma unroll
            for (int j = 0; j < 4; j++) {
                ulonglong2 qa = c2[2 * j];
                ulonglong2 qb = c2[2 * j + 1];
                a0 = fma2(xp[4 * j + 0], qa.x, a0);
                a1 = fma2(xp[4 * j + 1], qa.y, a1);
                a2 = fma2(xp[4 * j + 2], qb.x, a2);
                a3 = fma2(xp[4 * j + 3], qb.y, a3);
            }
            a0 = add2(a0, a1);
            a2 = add2(a2, a3);
            a0 = add2(a0, a2);
            float lo, hi;
            unpack2(a0, lo, hi);
            float dot = lo + hi;
            float sc = fmaf(-2.0f, dot, s_cn[piece][ff]);  // == d2 - ||x||^2
            int f = fstart + t + ff;
            if (sc < bd3) {
                if (sc < bd0) {
                    bd3 = bd2; bi3 = bi2; bd2 = bd1; bi2 = bi1; bd1 = bd0; bi1 = bi0;
                    bd0 = sc; bi0 = f;
                } else if (sc < bd1) {
                    bd3 = bd2; bi3 = bi2; bd2 = bd1; bi2 = bi1;
                    bd1 = sc; bi1 = f;
                } else if (sc < bd2) {
                    bd3 = bd2; bi3 = bi2;
                    bd2 = sc; bi2 = f;
                } else {
                    bd3 = sc; bi3 = f;
                }
            }
        }
    }

    // ---- publish candidates, merge 32 -> 4 per sample ----
    s_cd[s][piece * KNN + 0] = bd0;  s_ci[s][piece * KNN + 0] = bi0;
    s_cd[s][piece * KNN + 1] = bd1;  s_ci[s][piece * KNN + 1] = bi1;
    s_cd[s][piece * KNN + 2] = bd2;  s_ci[s][piece * KNN + 2] = bi2;
    s_cd[s][piece * KNN + 3] = bd3;  s_ci[s][piece * KNN + 3] = bi3;
    __syncthreads();

    if (threadIdx.x < SPB) {
        const int ms = threadIdx.x;       // sample this thread merges
        float cd[PIECES * KNN];
        int   ci[PIECES * KNN];
#pragma unroll
        for (int j = 0; j < PIECES * KNN; j++) {
            cd[j] = s_cd[ms][j];
            ci[j] = s_ci[ms][j];
        }
#pragma unroll
        for (int tt = 0; tt < KNN; tt++) {
            int best = 0;
#pragma unroll
            for (int j = 1; j < PIECES * KNN; j++) {
                // lexicographic (dist, idx): matches top_k tie-break by lower index
                if (cd[j] < cd[best] || (cd[j] == cd[best] && ci[j] < ci[best]))
                    best = j;
            }
            s_idx[ms][tt] = ci[best];
            cd[best] = 3.4e38f;
        }
    }
    __syncthreads();

    // ---- phase B: warp-cooperative apply, 4 samples per warp ----
    // lane = (row = lane>>3 in 0..3, e4 = lane&7): covers d in {row, row+4, ...}
    // and output columns [4*e4, 4*e4+4).
    const int row = lane >> 3;
    const int e4  = lane & 7;
    const float4* offs4 = (const float4*)offs;

    for (int si = 0; si < SPB / 4; si++) {
        const int sb = w * (SPB / 4) + si;
        float4 acc = make_float4(0.f, 0.f, 0.f, 0.f);
#pragma unroll
        for (int t = 0; t < KNN; t++) {
            int f = s_idx[sb][t];
            const float4* w4 = (const float4*)(wts + (size_t)f * D * D);
            const float*  cf = ctrs + (size_t)f * D;
#pragma unroll
            for (int dd = 0; dd < 8; dd++) {
                int d = dd * 4 + row;
                float4 wv = __ldg(w4 + d * 8 + e4);
                float  xc = s_x[sb][d] - __ldg(cf + d);
                acc.x = fmaf(xc, wv.x, acc.x);
                acc.y = fmaf(xc, wv.y, acc.y);
                acc.z = fmaf(xc, wv.z, acc.z);
                acc.w = fmaf(xc, wv.w, acc.w);
            }
        }
#pragma unroll
        for (int off = 8; off < 32; off <<= 1) {
            acc.x += __shfl_xor_sync(0xffffffffu, acc.x, off);
            acc.y += __shfl_xor_sync(0xffffffffu, acc.y, off);
            acc.z += __shfl_xor_sync(0xffffffffu, acc.z, off);
            acc.w += __shfl_xor_sync(0xffffffffu, acc.w, off);
        }
        if (row == 0) {
#pragma unroll
            for (int t = 0; t < KNN; t++) {
                int f = s_idx[sb][t];
                float4 ov = __ldg(offs4 + f * 8 + e4);
                acc.x += ov.x; acc.y += ov.y; acc.z += ov.z; acc.w += ov.w;
            }
            ((float4*)(y + (size_t)(blockIdx.x * SPB + sb) * D))[e4] = acc;
        }
    }
}

// ---------------- launch ----------------
extern "C" void kernel_launch(void* const* d_in, const int* in_sizes, int n_in,
                              void* d_out, int out_size)
{
    const float* x    = (const float*)d_in[0];
    const float* ctrs = (const float*)d_in[1];
    const float* wts  = (const float*)d_in[2];
    const float* offs = (const float*)d_in[3];
    float* y = (float*)d_out;

    int n_smps = in_sizes[0] / D;
    int n_fcns = in_sizes[1] / D;

    cnorm_kernel<<<(n_fcns + 255) / 256, 256>>>(ctrs, n_fcns);
    pwl_kernel<<<n_smps / SPB, 128>>>(x, ctrs, wts, offs, y, n_fcns);
}

// round 4
// speedup vs baseline: 1.1146x; 1.1146x over previous
#include <cuda_runtime.h>

typedef unsigned long long u64;

#define D      32
#define KNN    4
#define WARPS  6
#define SPB    32
#define TILE   32

// ---------------- packed f32x2 helpers (sm_103a FFMA2 path) ----------------
__device__ __forceinline__ u64 fma2(u64 a, u64 b, u64 c) {
    u64 r;
    asm("fma.rn.f32x2 %0, %1, %2, %3;" : "=l"(r) : "l"(a), "l"(b), "l"(c));
    return r;
}
__device__ __forceinline__ u64 add2(u64 a, u64 b) {
    u64 r;
    asm("add.rn.f32x2 %0, %1, %2;" : "=l"(r) : "l"(a), "l"(b));
    return r;
}
__device__ __forceinline__ void unpack2(u64 a, float& lo, float& hi) {
    asm("mov.b64 {%0, %1}, %2;" : "=f"(lo), "=f"(hi) : "l"(a));
}
__device__ __forceinline__ u64 pack2(float a, float b) {
    u64 r;
    asm("mov.b64 %0, {%1, %2};" : "=l"(r) : "f"(a), "f"(b));
    return r;
}

// ---------------- scratch: per-center squared norms ----------------
__device__ float g_cnorm[4096];

__global__ void cnorm_kernel(const float* __restrict__ ctrs, int n_fcns) {
    int f = blockIdx.x * blockDim.x + threadIdx.x;
    if (f < n_fcns) {
        const float4* c4 = (const float4*)(ctrs + (size_t)f * D);
        float s = 0.0f;
#pragma unroll
        for (int j = 0; j < D / 4; j++) {
            float4 q = __ldg(c4 + j);
            s += q.x * q.x + q.y * q.y + q.z * q.z + q.w * q.w;
        }
        g_cnorm[f] = s;
    }
}

// ---------------- main fused kernel ----------------
// Block = 192 threads = 6 warps, 32 samples (lane == sample).
// Phase A: warp w scans an uneven shard of ~341 centers keeping a per-lane
//          stable top-4 (single-branch SEL insertion). 24 candidates/sample.
// Phase B: warp w applies models for samples {w, w+6, ...} cooperatively.
__global__ __launch_bounds__(192, 4) void pwl_kernel(
    const float* __restrict__ x,
    const float* __restrict__ ctrs,
    const float* __restrict__ wts,
    const float* __restrict__ offs,
    float* __restrict__ y,
    int n_fcns)
{
    __shared__ __align__(16) float s_ctr[WARPS][TILE * D];   // 24 KB
    __shared__ float s_cn[WARPS][TILE];
    __shared__ float s_x[SPB][D + 1];
    __shared__ float s_cd[SPB][WARPS * KNN];
    __shared__ int   s_ci[SPB][WARPS * KNN];
    __shared__ int   s_idx[SPB][KNN];

    const int lane = threadIdx.x & 31;
    const int w    = threadIdx.x >> 5;
    const int srow = blockIdx.x * SPB + lane;

    // ---- load x row: registers hold packed (-2*x); smem holds raw x ----
    u64 xp[16];
    {
        const float4* xg = (const float4*)(x + (size_t)srow * D);
#pragma unroll
        for (int j = 0; j < 8; j++) {
            float4 q = __ldg(xg + j);
            if (w == 0) {
                s_x[lane][4 * j + 0] = q.x;
                s_x[lane][4 * j + 1] = q.y;
                s_x[lane][4 * j + 2] = q.z;
                s_x[lane][4 * j + 3] = q.w;
            }
            xp[2 * j]     = pack2(-2.0f * q.x, -2.0f * q.y);
            xp[2 * j + 1] = pack2(-2.0f * q.z, -2.0f * q.w);
        }
    }

    // ---- uneven shard bounds for this warp ----
    const int base = n_fcns / WARPS;
    const int rem  = n_fcns % WARPS;
    const int fstart = w * base + min(w, rem);
    const int fend   = fstart + base + (w < rem ? 1 : 0);

    float bd0 = 3.4e38f, bd1 = 3.4e38f, bd2 = 3.4e38f, bd3 = 3.4e38f;
    int   bi0 = 0, bi1 = 0, bi2 = 0, bi3 = 0;

    const float4* cg4 = (const float4*)ctrs;

    for (int t = fstart; t < fend; t += TILE) {
        __syncwarp();
        // stage TILE centers for this warp (clamped on last tile)
#pragma unroll
        for (int i = 0; i < TILE * D / 4 / 32; i++) {          // 8 iters
            int e  = i * 32 + lane;                            // 0..255
            int fr = min(t + (e >> 3), n_fcns - 1);
            ((float4*)s_ctr[w])[e] = __ldg(cg4 + (size_t)fr * 8 + (e & 7));
        }
        s_cn[w][lane] = g_cnorm[min(t + lane, n_fcns - 1)];
        __syncwarp();

        const int tile_n = min(TILE, fend - t);

#pragma unroll 2
        for (int ff = 0; ff < TILE; ff++) {
            const ulonglong2* c2 = (const ulonglong2*)(s_ctr[w] + ff * D);
            u64 a0 = 0ull, a1 = 0ull, a2 = 0ull;
            u64 a3 = (u64)__float_as_uint(s_cn[w][ff]);   // seed (cnorm, 0)
#pragma unroll
            for (int j = 0; j < 4; j++) {
                ulonglong2 qa = c2[2 * j];
                ulonglong2 qb = c2[2 * j + 1];
                a0 = fma2(xp[4 * j + 0], qa.x, a0);
                a1 = fma2(xp[4 * j + 1], qa.y, a1);
                a2 = fma2(xp[4 * j + 2], qb.x, a2);
                a3 = fma2(xp[4 * j + 3], qb.y, a3);
            }
            u64 r = add2(add2(a0, a1), add2(a2, a3));
            float lo, hi;
            unpack2(r, lo, hi);
            float sc = lo + hi;                 // == cnorm - 2*dot (rank-equiv)
            int f = t + ff;
            // single-branch, SEL-body stable insertion (strict <)
            if (sc < bd3 && ff < tile_n) {
                bool g0 = sc < bd0, g1 = sc < bd1, g2 = sc < bd2;
                float nb3 = g2 ? bd2 : sc;              int ni3 = g2 ? bi2 : f;
                float nb2 = g2 ? (g1 ? bd1 : sc) : bd2; int ni2 = g2 ? (g1 ? bi1 : f) : bi2;
                float nb1 = g1 ? (g0 ? bd0 : sc) : bd1; int ni1 = g1 ? (g0 ? bi0 : f) : bi1;
                bd0 = g0 ? sc : bd0;                    bi0 = g0 ? f : bi0;
                bd1 = nb1; bi1 = ni1;
                bd2 = nb2; bi2 = ni2;
                bd3 = nb3; bi3 = ni3;
            }
        }
    }

    // ---- publish candidates, merge 24 -> 4 per sample ----
    s_cd[lane][w * KNN + 0] = bd0;  s_ci[lane][w * KNN + 0] = bi0;
    s_cd[lane][w * KNN + 1] = bd1;  s_ci[lane][w * KNN + 1] = bi1;
    s_cd[lane][w * KNN + 2] = bd2;  s_ci[lane][w * KNN + 2] = bi2;
    s_cd[lane][w * KNN + 3] = bd3;  s_ci[lane][w * KNN + 3] = bi3;
    __syncthreads();

    if (threadIdx.x < SPB) {
        const int ms = threadIdx.x;
        float cd[WARPS * KNN];
        int   ci[WARPS * KNN];
#pragma unroll
        for (int j = 0; j < WARPS * KNN; j++) {
            cd[j] = s_cd[ms][j];
            ci[j] = s_ci[ms][j];
        }
#pragma unroll
        for (int tt = 0; tt < KNN; tt++) {
            int best = 0;
#pragma unroll
            for (int j = 1; j < WARPS * KNN; j++) {
                // lexicographic (dist, idx): matches top_k tie-break
                if (cd[j] < cd[best] || (cd[j] == cd[best] && ci[j] < ci[best]))
                    best = j;
            }
            s_idx[ms][tt] = ci[best];
            cd[best] = 3.4e38f;
        }
    }
    __syncthreads();

    // ---- phase B: warp-cooperative apply ----
    // lane = (row = lane>>3 in 0..3, e4 = lane&7): covers d in {row, row+4, ...}
    // and output columns [4*e4, 4*e4+4).
    const int row = lane >> 3;
    const int e4  = lane & 7;
    const float4* offs4 = (const float4*)offs;

    for (int sb = w; sb < SPB; sb += WARPS) {
        float4 acc = make_float4(0.f, 0.f, 0.f, 0.f);
#pragma unroll
        for (int t = 0; t < KNN; t++) {
            int f = s_idx[sb][t];
            const float4* w4 = (const float4*)(wts + (size_t)f * D * D);
            const float*  cf = ctrs + (size_t)f * D;
#pragma unroll
            for (int dd = 0; dd < 8; dd++) {
                int d = dd * 4 + row;
                float4 wv = __ldg(w4 + d * 8 + e4);
                float  xc = s_x[sb][d] - __ldg(cf + d);
                acc.x = fmaf(xc, wv.x, acc.x);
                acc.y = fmaf(xc, wv.y, acc.y);
                acc.z = fmaf(xc, wv.z, acc.z);
                acc.w = fmaf(xc, wv.w, acc.w);
            }
        }
#pragma unroll
        for (int off = 8; off < 32; off <<= 1) {
            acc.x += __shfl_xor_sync(0xffffffffu, acc.x, off);
            acc.y += __shfl_xor_sync(0xffffffffu, acc.y, off);
            acc.z += __shfl_xor_sync(0xffffffffu, acc.z, off);
            acc.w += __shfl_xor_sync(0xffffffffu, acc.w, off);
        }
        if (row == 0) {
#pragma unroll
            for (int t = 0; t < KNN; t++) {
                int f = s_idx[sb][t];
                float4 ov = __ldg(offs4 + f * 8 + e4);
                acc.x += ov.x; acc.y += ov.y; acc.z += ov.z; acc.w += ov.w;
            }
            ((float4*)(y + (size_t)(blockIdx.x * SPB + sb) * D))[e4] = acc;
        }
    }
}

// ---------------- launch ----------------
extern "C" void kernel_launch(void* const* d_in, const int* in_sizes, int n_in,
                              void* d_out, int out_size)
{
    const float* x    = (const float*)d_in[0];
    const float* ctrs = (const float*)d_in[1];
    const float* wts  = (const float*)d_in[2];
    const float* offs = (const float*)d_in[3];
    float* y = (float*)d_out;

    int n_smps = in_sizes[0] / D;
    int n_fcns = in_sizes[1] / D;

    cnorm_kernel<<<(n_fcns + 255) / 256, 256>>>(ctrs, n_fcns);
    pwl_kernel<<<n_smps / SPB, 192>>>(x, ctrs, wts, offs, y, n_fcns);
}